// round 1
// baseline (speedup 1.0000x reference)
#include <cuda_runtime.h>
#include <math.h>

#define MAXN 1025
#define BATCH 8
#define C 128
#define NH 8
#define HD 16
#define L 4

// ---------------- device scratch (static, allocation-free) ----------------
__device__ float g_X0[BATCH*MAXN*C];
__device__ float g_X1[BATCH*MAXN*C];
__device__ float g_Y [BATCH*MAXN*C];
__device__ float g_QKV[BATCH*MAXN*384];
__device__ float g_O [BATCH*MAXN*C];
__device__ float g_H [BATCH*MAXN*512];
__device__ float g_CLSP[BATCH*NH*MAXN];
__device__ float g_WT[768*128];
__device__ int   g_order[BATCH][1024];
__device__ int   g_count[BATCH];
__device__ int   g_mk[3];
__device__ int   g_N;

// ---------------- init ----------------
__global__ void k_init() {
    g_N = MAXN;
    g_mk[0] = 0; g_mk[1] = 0; g_mk[2] = 0;
}

// transpose conv_w (128,768) -> (768,128) for coalesced patch GEMM
__global__ void k_transpose(const float* __restrict__ w) {
    int k = blockIdx.x, c = threadIdx.x;
    g_WT[k*128 + c] = w[c*768 + k];
}

// ---------------- patch embed: tok = xr @ W^T + b ; X = tok + pos ----------
// grid (128, 8), block 128. 8 patches per block.
__global__ void k_patch(const float* __restrict__ x, const float* __restrict__ cb,
                        const float* __restrict__ pos, float* __restrict__ X) {
    int b = blockIdx.y;
    int t0 = blockIdx.x * 8;
    __shared__ float sP[8][768];
    int tid = threadIdx.x;
    for (int idx = tid; idx < 8*768; idx += 128) {
        int p = idx / 768, k = idx % 768;
        int t = t0 + p;
        int ph = t >> 5, pw = t & 31;
        int ch = k >> 8, rem = k & 255, py = rem >> 4, px = rem & 15;
        sP[p][k] = x[((size_t)(b*3 + ch)*512 + ph*16 + py)*512 + pw*16 + px];
    }
    __syncthreads();
    float acc[8];
    float bias = cb[tid];
    #pragma unroll
    for (int p = 0; p < 8; p++) acc[p] = bias;
    for (int k = 0; k < 768; k++) {
        float w = g_WT[k*128 + tid];
        #pragma unroll
        for (int p = 0; p < 8; p++) acc[p] += w * sP[p][k];
    }
    #pragma unroll
    for (int p = 0; p < 8; p++) {
        int t = t0 + p;
        X[((size_t)b*MAXN + 1 + t)*C + tid] = acc[p] + pos[(1 + t)*C + tid];
    }
}

// cls row: X[b,0,:] = cls + pos[0]
__global__ void k_cls(const float* __restrict__ cls, const float* __restrict__ pos,
                      float* __restrict__ X) {
    int b = blockIdx.x, c = threadIdx.x;
    X[(size_t)b*MAXN*C + c] = cls[c] + pos[c];
}

// ---------------- layernorm: Y = LN(X)*w + b  (grid (1025,8), block 128) ----
__global__ void k_ln(const float* __restrict__ X, float* __restrict__ Y,
                     const float* __restrict__ w, const float* __restrict__ bb) {
    int n = blockIdx.x, b = blockIdx.y;
    if (n >= g_N) return;
    int c = threadIdx.x;
    __shared__ float red[4];
    size_t base = ((size_t)b*MAXN + n) * C;
    float v = X[base + c];
    float s = v;
    #pragma unroll
    for (int o = 16; o; o >>= 1) s += __shfl_xor_sync(0xffffffffu, s, o);
    if ((c & 31) == 0) red[c >> 5] = s;
    __syncthreads();
    float mu = (red[0] + red[1] + red[2] + red[3]) * (1.0f/128.0f);
    __syncthreads();
    float d = v - mu;
    float s2 = d * d;
    #pragma unroll
    for (int o = 16; o; o >>= 1) s2 += __shfl_xor_sync(0xffffffffu, s2, o);
    if ((c & 31) == 0) red[c >> 5] = s2;
    __syncthreads();
    float var = (red[0] + red[1] + red[2] + red[3]) * (1.0f/128.0f);
    float rs = 1.0f / sqrtf(var + 1e-5f);
    Y[base + c] = d * rs * w[c] + bb[c];
}

// ---------------- qkv: QKV = Y @ W(128x384) + b  (8 tokens / block) --------
__global__ void k_qkv(const float* __restrict__ Y, const float* __restrict__ W,
                      const float* __restrict__ bias, float* __restrict__ QKV) {
    int b = blockIdx.y;
    int n0 = blockIdx.x * 8;
    int N = g_N;
    if (n0 >= N) return;
    __shared__ float sY[8][C];
    int tid = threadIdx.x;
    #pragma unroll
    for (int p = 0; p < 8; p++) {
        int n = n0 + p;
        sY[p][tid] = (n < N) ? Y[((size_t)b*MAXN + n)*C + tid] : 0.0f;
    }
    __syncthreads();
    float a0[8], a1[8], a2[8];
    float b0 = bias[tid], b1 = bias[tid + 128], b2 = bias[tid + 256];
    #pragma unroll
    for (int p = 0; p < 8; p++) { a0[p] = b0; a1[p] = b1; a2[p] = b2; }
    for (int k = 0; k < 128; k++) {
        float w0 = W[k*384 + tid];
        float w1 = W[k*384 + tid + 128];
        float w2 = W[k*384 + tid + 256];
        #pragma unroll
        for (int p = 0; p < 8; p++) {
            float y = sY[p][k];
            a0[p] += w0 * y; a1[p] += w1 * y; a2[p] += w2 * y;
        }
    }
    #pragma unroll
    for (int p = 0; p < 8; p++) {
        int n = n0 + p;
        if (n < N) {
            size_t o = ((size_t)b*MAXN + n) * 384;
            QKV[o + tid] = a0[p];
            QKV[o + 128 + tid] = a1[p];
            QKV[o + 256 + tid] = a2[p];
        }
    }
}

// ---------------- attention: grid (1025, 8), block 256 (warp = head) -------
__global__ void k_attn(const float* __restrict__ QKV, float* __restrict__ O) {
    int q = blockIdx.x, b = blockIdx.y;
    int N = g_N;
    if (q >= N) return;
    int tid = threadIdx.x;
    int h = tid >> 5, lane = tid & 31;
    const float* qp = QKV + ((size_t)(b*MAXN + q))*384 + h*HD;
    float qv[HD];
    #pragma unroll
    for (int d = 0; d < HD; d++) qv[d] = qp[d];
    const float* Kb = QKV + (size_t)b*MAXN*384 + 128 + h*HD;
    const float* Vb = Kb + 128;

    float mx = -1e30f;
    for (int m = lane; m < N; m += 32) {
        const float* kp = Kb + (size_t)m*384;
        float s = 0.0f;
        #pragma unroll
        for (int d = 0; d < HD; d++) s += qv[d] * kp[d];
        mx = fmaxf(mx, s * 0.25f);
    }
    #pragma unroll
    for (int o = 16; o; o >>= 1) mx = fmaxf(mx, __shfl_xor_sync(0xffffffffu, mx, o));

    float sum = 0.0f, e0 = 0.0f;
    float acc[HD];
    #pragma unroll
    for (int d = 0; d < HD; d++) acc[d] = 0.0f;
    for (int m = lane; m < N; m += 32) {
        const float* kp = Kb + (size_t)m*384;
        float s = 0.0f;
        #pragma unroll
        for (int d = 0; d < HD; d++) s += qv[d] * kp[d];
        float e = expf(s * 0.25f - mx);
        sum += e;
        if (m == 0) e0 = e;
        const float* vp = Vb + (size_t)m*384;
        #pragma unroll
        for (int d = 0; d < HD; d++) acc[d] += e * vp[d];
    }
    #pragma unroll
    for (int o = 16; o; o >>= 1) sum += __shfl_xor_sync(0xffffffffu, sum, o);
    #pragma unroll
    for (int d = 0; d < HD; d++) {
        float a = acc[d];
        #pragma unroll
        for (int o = 16; o; o >>= 1) a += __shfl_xor_sync(0xffffffffu, a, o);
        acc[d] = a;
    }
    if (lane == 0) {
        float inv = 1.0f / sum;
        size_t ob = ((size_t)b*MAXN + q)*C + h*HD;
        #pragma unroll
        for (int d = 0; d < HD; d++) O[ob + d] = acc[d] * inv;
        g_CLSP[(b*NH + h)*MAXN + q] = e0 * inv;
    }
}

// ---------------- out proj: X += O @ W(128x128) + b ------------------------
__global__ void k_proj(const float* __restrict__ Oin, const float* __restrict__ W,
                       const float* __restrict__ bias, float* __restrict__ X) {
    int b = blockIdx.y;
    int n0 = blockIdx.x * 8;
    int N = g_N;
    if (n0 >= N) return;
    __shared__ float sO[8][C];
    int tid = threadIdx.x;
    #pragma unroll
    for (int p = 0; p < 8; p++) {
        int n = n0 + p;
        sO[p][tid] = (n < N) ? Oin[((size_t)b*MAXN + n)*C + tid] : 0.0f;
    }
    __syncthreads();
    float acc[8];
    float bs = bias[tid];
    #pragma unroll
    for (int p = 0; p < 8; p++) acc[p] = bs;
    for (int k = 0; k < 128; k++) {
        float w = W[k*128 + tid];
        #pragma unroll
        for (int p = 0; p < 8; p++) acc[p] += w * sO[p][k];
    }
    #pragma unroll
    for (int p = 0; p < 8; p++) {
        int n = n0 + p;
        if (n < N) X[((size_t)b*MAXN + n)*C + tid] += acc[p];
    }
}

// ---------------- fc1 + exact gelu: H = gelu(Y @ W1(128x512) + b1) ---------
__global__ void k_fc1(const float* __restrict__ Y, const float* __restrict__ W,
                      const float* __restrict__ bias, float* __restrict__ H) {
    int b = blockIdx.y;
    int n0 = blockIdx.x * 8;
    int N = g_N;
    if (n0 >= N) return;
    __shared__ float sY[8][C];
    int tid = threadIdx.x;
    #pragma unroll
    for (int p = 0; p < 8; p++) {
        int n = n0 + p;
        sY[p][tid] = (n < N) ? Y[((size_t)b*MAXN + n)*C + tid] : 0.0f;
    }
    __syncthreads();
    float a[4][8];
    #pragma unroll
    for (int r = 0; r < 4; r++) {
        float bs = bias[tid + 128*r];
        #pragma unroll
        for (int p = 0; p < 8; p++) a[r][p] = bs;
    }
    for (int k = 0; k < 128; k++) {
        float w0 = W[k*512 + tid];
        float w1 = W[k*512 + tid + 128];
        float w2 = W[k*512 + tid + 256];
        float w3 = W[k*512 + tid + 384];
        #pragma unroll
        for (int p = 0; p < 8; p++) {
            float y = sY[p][k];
            a[0][p] += w0 * y; a[1][p] += w1 * y; a[2][p] += w2 * y; a[3][p] += w3 * y;
        }
    }
    #pragma unroll
    for (int p = 0; p < 8; p++) {
        int n = n0 + p;
        if (n < N) {
            size_t o = ((size_t)b*MAXN + n) * 512;
            #pragma unroll
            for (int r = 0; r < 4; r++) {
                float v = a[r][p];
                float g = 0.5f * v * (1.0f + erff(v * 0.70710678118654752f));
                H[o + tid + 128*r] = g;
            }
        }
    }
}

// ---------------- fc2: X += H @ W2(512x128) + b2 ---------------------------
__global__ void k_fc2(const float* __restrict__ H, const float* __restrict__ W,
                      const float* __restrict__ bias, float* __restrict__ X) {
    int b = blockIdx.y;
    int n0 = blockIdx.x * 8;
    int N = g_N;
    if (n0 >= N) return;
    __shared__ float sH[8][512];
    int tid = threadIdx.x;
    for (int idx = tid; idx < 8*512; idx += 128) {
        int p = idx >> 9, k = idx & 511;
        int n = n0 + p;
        sH[p][k] = (n < N) ? H[((size_t)b*MAXN + n)*512 + k] : 0.0f;
    }
    __syncthreads();
    float acc[8];
    float bs = bias[tid];
    #pragma unroll
    for (int p = 0; p < 8; p++) acc[p] = bs;
    for (int k = 0; k < 512; k++) {
        float w = W[k*128 + tid];
        #pragma unroll
        for (int p = 0; p < 8; p++) acc[p] += w * sH[p][k];
    }
    #pragma unroll
    for (int p = 0; p < 8; p++) {
        int n = n0 + p;
        if (n < N) X[((size_t)b*MAXN + n)*C + tid] += acc[p];
    }
}

// ---------------- prune stage 1: keep flags, compact order, count, mk ------
__global__ void k_prune1(float thresh, int pi) {
    int b = blockIdx.x;
    int t = threadIdx.x;
    int tc = g_N - 1;
    __shared__ int ssum[1024];
    __shared__ float sval[1024];
    __shared__ int sidx[1024];
    float am = -1e30f;
    int keep = 0;
    if (t < tc) {
        float s = 0.0f;
        #pragma unroll
        for (int h = 0; h < NH; h++) s += g_CLSP[(b*NH + h)*MAXN + 1 + t];
        am = s * 0.125f;
        keep = (am > thresh) ? 1 : 0;
    }
    ssum[t] = keep; sval[t] = am; sidx[t] = t;
    __syncthreads();
    // argmax (first index on ties) for fallback
    for (int off = 512; off > 0; off >>= 1) {
        if (t < off) {
            if (sval[t + off] > sval[t] ||
                (sval[t + off] == sval[t] && sidx[t + off] < sidx[t])) {
                sval[t] = sval[t + off]; sidx[t] = sidx[t + off];
            }
        }
        __syncthreads();
    }
    int argidx = sidx[0];
    __syncthreads();
    // inclusive scan of keep flags
    for (int off = 1; off < 1024; off <<= 1) {
        int v = (t >= off) ? ssum[t - off] : 0;
        __syncthreads();
        ssum[t] += v;
        __syncthreads();
    }
    int total = ssum[1023];
    if (total > 0 && keep) g_order[b][ssum[t] - 1] = t;
    if (t == 0) {
        int cnt = total;
        if (total == 0) { g_order[b][0] = argidx; cnt = 1; }
        g_count[b] = cnt;
        atomicMax(&g_mk[pi], cnt);
    }
}

// ---------------- prune stage 2: gather into other buffer + pos ------------
__global__ void k_prune2(const float* __restrict__ Xold, float* __restrict__ Xnew,
                         const float* __restrict__ pos, int pi) {
    int b = blockIdx.y, c = threadIdx.x;
    int mk = g_mk[pi];
    if (blockIdx.x == 0) {
        Xnew[(size_t)b*MAXN*C + c] = Xold[(size_t)b*MAXN*C + c] + pos[c];
        if (b == 0 && c == 0) g_N = 1 + mk;
        return;
    }
    int j = blockIdx.x - 1;
    if (j >= mk) return;
    float v = 0.0f;
    if (j < g_count[b]) {
        int src = g_order[b][j];
        v = Xold[((size_t)b*MAXN + 1 + src)*C + c];
    }
    Xnew[((size_t)b*MAXN + 1 + j)*C + c] = v + pos[(1 + j)*C + c];
}

// ---------------- output copy ----------------------------------------------
__global__ void k_copy(const float* __restrict__ X, float* __restrict__ out,
                       int finalN, int total) {
    int idx = blockIdx.x * 256 + threadIdx.x;
    if (idx >= total) return;
    int per = finalN * C;
    int b = idx / per;
    int rem = idx - b * per;
    out[idx] = X[(size_t)b*MAXN*C + rem];
}

// ---------------- host orchestration ----------------------------------------
extern "C" void kernel_launch(void* const* d_in, const int* in_sizes, int n_in,
                              void* d_out, int out_size) {
    const float* conv_w   = (const float*)d_in[0];
    const float* conv_b   = (const float*)d_in[1];
    const float* cls_tok  = (const float*)d_in[2];
    const float* pos      = (const float*)d_in[3];
    const float* ln1_w    = (const float*)d_in[4];
    const float* ln1_b    = (const float*)d_in[5];
    const float* qkv_w    = (const float*)d_in[6];
    const float* qkv_b    = (const float*)d_in[7];
    const float* out_w    = (const float*)d_in[8];
    const float* out_b    = (const float*)d_in[9];
    const float* ln2_w    = (const float*)d_in[10];
    const float* ln2_b    = (const float*)d_in[11];
    const float* mlp_w1   = (const float*)d_in[12];
    const float* mlp_b1   = (const float*)d_in[13];
    const float* mlp_w2   = (const float*)d_in[14];
    const float* mlp_b2   = (const float*)d_in[15];
    const float* x        = (const float*)d_in[16];
    float* out = (float*)d_out;

    float *pX0, *pX1, *pY, *pQKV, *pO, *pH;
    cudaGetSymbolAddress((void**)&pX0,  g_X0);
    cudaGetSymbolAddress((void**)&pX1,  g_X1);
    cudaGetSymbolAddress((void**)&pY,   g_Y);
    cudaGetSymbolAddress((void**)&pQKV, g_QKV);
    cudaGetSymbolAddress((void**)&pO,   g_O);
    cudaGetSymbolAddress((void**)&pH,   g_H);

    const float THRESH[3] = {0.001f, 0.0012f, 0.0015f};

    k_init<<<1, 1>>>();
    k_transpose<<<768, 128>>>(conv_w);
    k_patch<<<dim3(128, BATCH), 128>>>(x, conv_b, pos, pX0);
    k_cls<<<BATCH, 128>>>(cls_tok, pos, pX0);

    float* cur = pX0;
    float* alt = pX1;
    dim3 gTok(MAXN, BATCH);
    dim3 gBlk(129, BATCH);   // ceil(1025/8)

    for (int i = 0; i < L; i++) {
        k_ln  <<<gTok, 128>>>(cur, pY, ln1_w + i*C, ln1_b + i*C);
        k_qkv <<<gBlk, 128>>>(pY, qkv_w + (size_t)i*C*384, qkv_b + i*384, pQKV);
        k_attn<<<gTok, 256>>>(pQKV, pO);
        k_proj<<<gBlk, 128>>>(pO, out_w + (size_t)i*C*C, out_b + i*C, cur);
        k_ln  <<<gTok, 128>>>(cur, pY, ln2_w + i*C, ln2_b + i*C);
        k_fc1 <<<gBlk, 128>>>(pY, mlp_w1 + (size_t)i*C*512, mlp_b1 + i*512, pH);
        k_fc2 <<<gBlk, 128>>>(pH, mlp_w2 + (size_t)i*512*C, mlp_b2 + i*C, cur);
        if (i < L - 1) {
            k_prune1<<<BATCH, 1024>>>(THRESH[i], i);
            k_prune2<<<gTok, 128>>>(cur, alt, pos, i);
            float* tmp = cur; cur = alt; alt = tmp;
        }
    }

    int finalN = out_size / (BATCH * C);
    int nblk = (out_size + 255) / 256;
    k_copy<<<nblk, 256>>>(cur, out, finalN, out_size);
}

// round 2
// speedup vs baseline: 14.6809x; 14.6809x over previous
#include <cuda_runtime.h>
#include <math.h>

#define MAXN 1025
#define BATCH 8
#define C 128
#define NH 8
#define HD 16
#define L 4
#define TK 256

// ---------------- device scratch (static, allocation-free) ----------------
__device__ float g_X0[BATCH*MAXN*C];
__device__ float g_X1[BATCH*MAXN*C];
__device__ float g_Y [BATCH*MAXN*C];
__device__ float g_Q [BATCH*NH*MAXN*HD];
__device__ float g_K [BATCH*NH*MAXN*HD];
__device__ float g_V [BATCH*NH*MAXN*HD];
__device__ float g_O [BATCH*MAXN*C];
__device__ float g_H [BATCH*MAXN*512];
__device__ float g_CLSP[BATCH*NH*MAXN];
__device__ float g_WT[768*128];
__device__ int   g_order[BATCH][1024];
__device__ int   g_count[BATCH];
__device__ int   g_mk[3];
__device__ int   g_N;

// ---------------- init ----------------
__global__ void k_init() {
    g_N = MAXN;
    g_mk[0] = 0; g_mk[1] = 0; g_mk[2] = 0;
}

// transpose conv_w (128,768) -> (768,128) for coalesced patch GEMM
__global__ void k_transpose(const float* __restrict__ w) {
    int k = blockIdx.x, c = threadIdx.x;
    g_WT[k*128 + c] = w[c*768 + k];
}

// ---------------- patch embed: tok = xr @ W^T + b ; X = tok + pos ----------
__global__ void k_patch(const float* __restrict__ x, const float* __restrict__ cb,
                        const float* __restrict__ pos, float* __restrict__ X) {
    int b = blockIdx.y;
    int t0 = blockIdx.x * 8;
    __shared__ float sP[8][768];
    int tid = threadIdx.x;
    for (int idx = tid; idx < 8*768; idx += 128) {
        int p = idx / 768, k = idx % 768;
        int t = t0 + p;
        int ph = t >> 5, pw = t & 31;
        int ch = k >> 8, rem = k & 255, py = rem >> 4, px = rem & 15;
        sP[p][k] = x[((size_t)(b*3 + ch)*512 + ph*16 + py)*512 + pw*16 + px];
    }
    __syncthreads();
    float acc[8];
    float bias = cb[tid];
    #pragma unroll
    for (int p = 0; p < 8; p++) acc[p] = bias;
    for (int k = 0; k < 768; k++) {
        float w = g_WT[k*128 + tid];
        #pragma unroll
        for (int p = 0; p < 8; p++) acc[p] += w * sP[p][k];
    }
    #pragma unroll
    for (int p = 0; p < 8; p++) {
        int t = t0 + p;
        X[((size_t)b*MAXN + 1 + t)*C + tid] = acc[p] + pos[(1 + t)*C + tid];
    }
}

__global__ void k_cls(const float* __restrict__ cls, const float* __restrict__ pos,
                      float* __restrict__ X) {
    int b = blockIdx.x, c = threadIdx.x;
    X[(size_t)b*MAXN*C + c] = cls[c] + pos[c];
}

// ---------------- layernorm ----------------
__global__ void k_ln(const float* __restrict__ X, float* __restrict__ Y,
                     const float* __restrict__ w, const float* __restrict__ bb) {
    int n = blockIdx.x, b = blockIdx.y;
    if (n >= g_N) return;
    int c = threadIdx.x;
    __shared__ float red[4];
    size_t base = ((size_t)b*MAXN + n) * C;
    float v = X[base + c];
    float s = v;
    #pragma unroll
    for (int o = 16; o; o >>= 1) s += __shfl_xor_sync(0xffffffffu, s, o);
    if ((c & 31) == 0) red[c >> 5] = s;
    __syncthreads();
    float mu = (red[0] + red[1] + red[2] + red[3]) * (1.0f/128.0f);
    __syncthreads();
    float d = v - mu;
    float s2 = d * d;
    #pragma unroll
    for (int o = 16; o; o >>= 1) s2 += __shfl_xor_sync(0xffffffffu, s2, o);
    if ((c & 31) == 0) red[c >> 5] = s2;
    __syncthreads();
    float var = (red[0] + red[1] + red[2] + red[3]) * (1.0f/128.0f);
    float rs = 1.0f / sqrtf(var + 1e-5f);
    Y[base + c] = d * rs * w[c] + bb[c];
}

// ---------------- qkv -> head-major Q,K,V [b,h,n,16] -----------------------
__global__ void k_qkv(const float* __restrict__ Y, const float* __restrict__ W,
                      const float* __restrict__ bias,
                      float* __restrict__ Qo, float* __restrict__ Ko,
                      float* __restrict__ Vo) {
    int b = blockIdx.y;
    int n0 = blockIdx.x * 8;
    int N = g_N;
    if (n0 >= N) return;
    __shared__ float sY[8][C];
    int tid = threadIdx.x;
    #pragma unroll
    for (int p = 0; p < 8; p++) {
        int n = n0 + p;
        sY[p][tid] = (n < N) ? Y[((size_t)b*MAXN + n)*C + tid] : 0.0f;
    }
    __syncthreads();
    float a0[8], a1[8], a2[8];
    float b0 = bias[tid], b1 = bias[tid + 128], b2 = bias[tid + 256];
    #pragma unroll
    for (int p = 0; p < 8; p++) { a0[p] = b0; a1[p] = b1; a2[p] = b2; }
    for (int k = 0; k < 128; k++) {
        float w0 = W[k*384 + tid];
        float w1 = W[k*384 + tid + 128];
        float w2 = W[k*384 + tid + 256];
        #pragma unroll
        for (int p = 0; p < 8; p++) {
            float y = sY[p][k];
            a0[p] += w0 * y; a1[p] += w1 * y; a2[p] += w2 * y;
        }
    }
    int h = tid >> 4, d = tid & 15;
    #pragma unroll
    for (int p = 0; p < 8; p++) {
        int n = n0 + p;
        if (n < N) {
            size_t o = ((size_t)(b*NH + h)*MAXN + n)*HD + d;
            Qo[o] = a0[p]; Ko[o] = a1[p]; Vo[o] = a2[p];
        }
    }
}

// ---------------- attention: 1 query/lane, K/V tiled thru smem -------------
// grid (ceil(MAXN/256), B*NH), block 256
__global__ void __launch_bounds__(256) k_attn2(
        const float* __restrict__ Q, const float* __restrict__ K,
        const float* __restrict__ V, float* __restrict__ O) {
    int N = g_N;
    int bh = blockIdx.y;
    int b = bh >> 3, h = bh & 7;
    int q0 = blockIdx.x * 256;
    if (q0 >= N) return;
    int tid = threadIdx.x;
    __shared__ float4 sK[TK*4];
    __shared__ float4 sV[TK*4];
    const float* Kb = K + (size_t)bh*MAXN*HD;
    const float* Vb = V + (size_t)bh*MAXN*HD;
    int q = q0 + tid;

    float qv[16];
    if (q < N) {
        const float4* Q4 = (const float4*)(Q + ((size_t)bh*MAXN + q)*HD);
        float4 t0 = Q4[0], t1 = Q4[1], t2 = Q4[2], t3 = Q4[3];
        qv[0]=t0.x; qv[1]=t0.y; qv[2]=t0.z; qv[3]=t0.w;
        qv[4]=t1.x; qv[5]=t1.y; qv[6]=t1.z; qv[7]=t1.w;
        qv[8]=t2.x; qv[9]=t2.y; qv[10]=t2.z; qv[11]=t2.w;
        qv[12]=t3.x; qv[13]=t3.y; qv[14]=t3.z; qv[15]=t3.w;
    }

    float m_run = -1e30f, l_run = 0.0f;
    float acc[16];
    #pragma unroll
    for (int d = 0; d < 16; d++) acc[d] = 0.0f;

    int nt = (N + TK - 1) / TK;
    for (int t = 0; t < nt; t++) {
        int base = t * TK;
        int kn = min(TK, N - base);
        __syncthreads();
        const float4* K4 = (const float4*)(Kb + (size_t)base*HD);
        const float4* V4 = (const float4*)(Vb + (size_t)base*HD);
        for (int i = tid; i < kn*4; i += 256) { sK[i] = K4[i]; sV[i] = V4[i]; }
        __syncthreads();
        if (q < N) {
            for (int m = 0; m < kn; m++) {
                float4 k0 = sK[m*4], k1 = sK[m*4+1], k2 = sK[m*4+2], k3 = sK[m*4+3];
                float s = qv[0]*k0.x + qv[1]*k0.y + qv[2]*k0.z + qv[3]*k0.w
                        + qv[4]*k1.x + qv[5]*k1.y + qv[6]*k1.z + qv[7]*k1.w
                        + qv[8]*k2.x + qv[9]*k2.y + qv[10]*k2.z + qv[11]*k2.w
                        + qv[12]*k3.x + qv[13]*k3.y + qv[14]*k3.z + qv[15]*k3.w;
                s *= 0.25f;
                if (s > m_run) {
                    float corr = expf(m_run - s);
                    l_run *= corr;
                    #pragma unroll
                    for (int d = 0; d < 16; d++) acc[d] *= corr;
                    m_run = s;
                }
                float e = expf(s - m_run);
                l_run += e;
                float4 v0 = sV[m*4], v1 = sV[m*4+1], v2 = sV[m*4+2], v3 = sV[m*4+3];
                acc[0]+=e*v0.x; acc[1]+=e*v0.y; acc[2]+=e*v0.z; acc[3]+=e*v0.w;
                acc[4]+=e*v1.x; acc[5]+=e*v1.y; acc[6]+=e*v1.z; acc[7]+=e*v1.w;
                acc[8]+=e*v2.x; acc[9]+=e*v2.y; acc[10]+=e*v2.z; acc[11]+=e*v2.w;
                acc[12]+=e*v3.x; acc[13]+=e*v3.y; acc[14]+=e*v3.z; acc[15]+=e*v3.w;
            }
        }
    }

    if (q < N) {
        float inv = 1.0f / l_run;
        // CLS-key probability: recompute s0 exactly
        const float4* k04 = (const float4*)Kb;
        float4 k0 = k04[0], k1 = k04[1], k2 = k04[2], k3 = k04[3];
        float s0 = qv[0]*k0.x + qv[1]*k0.y + qv[2]*k0.z + qv[3]*k0.w
                 + qv[4]*k1.x + qv[5]*k1.y + qv[6]*k1.z + qv[7]*k1.w
                 + qv[8]*k2.x + qv[9]*k2.y + qv[10]*k2.z + qv[11]*k2.w
                 + qv[12]*k3.x + qv[13]*k3.y + qv[14]*k3.z + qv[15]*k3.w;
        s0 *= 0.25f;
        g_CLSP[(size_t)bh*MAXN + q] = expf(s0 - m_run) * inv;
        float* op = O + ((size_t)b*MAXN + q)*C + h*HD;
        #pragma unroll
        for (int d = 0; d < 16; d++) op[d] = acc[d] * inv;
    }
}

// ---------------- out proj: X += O @ W(128x128) + b ------------------------
__global__ void k_proj(const float* __restrict__ Oin, const float* __restrict__ W,
                       const float* __restrict__ bias, float* __restrict__ X) {
    int b = blockIdx.y;
    int n0 = blockIdx.x * 8;
    int N = g_N;
    if (n0 >= N) return;
    __shared__ float sO[8][C];
    int tid = threadIdx.x;
    #pragma unroll
    for (int p = 0; p < 8; p++) {
        int n = n0 + p;
        sO[p][tid] = (n < N) ? Oin[((size_t)b*MAXN + n)*C + tid] : 0.0f;
    }
    __syncthreads();
    float acc[8];
    float bs = bias[tid];
    #pragma unroll
    for (int p = 0; p < 8; p++) acc[p] = bs;
    for (int k = 0; k < 128; k++) {
        float w = W[k*128 + tid];
        #pragma unroll
        for (int p = 0; p < 8; p++) acc[p] += w * sO[p][k];
    }
    #pragma unroll
    for (int p = 0; p < 8; p++) {
        int n = n0 + p;
        if (n < N) X[((size_t)b*MAXN + n)*C + tid] += acc[p];
    }
}

// ---------------- fc1 + exact gelu -----------------------------------------
__global__ void k_fc1(const float* __restrict__ Y, const float* __restrict__ W,
                      const float* __restrict__ bias, float* __restrict__ H) {
    int b = blockIdx.y;
    int n0 = blockIdx.x * 8;
    int N = g_N;
    if (n0 >= N) return;
    __shared__ float sY[8][C];
    int tid = threadIdx.x;
    #pragma unroll
    for (int p = 0; p < 8; p++) {
        int n = n0 + p;
        sY[p][tid] = (n < N) ? Y[((size_t)b*MAXN + n)*C + tid] : 0.0f;
    }
    __syncthreads();
    float a[4][8];
    #pragma unroll
    for (int r = 0; r < 4; r++) {
        float bs = bias[tid + 128*r];
        #pragma unroll
        for (int p = 0; p < 8; p++) a[r][p] = bs;
    }
    for (int k = 0; k < 128; k++) {
        float w0 = W[k*512 + tid];
        float w1 = W[k*512 + tid + 128];
        float w2 = W[k*512 + tid + 256];
        float w3 = W[k*512 + tid + 384];
        #pragma unroll
        for (int p = 0; p < 8; p++) {
            float y = sY[p][k];
            a[0][p] += w0 * y; a[1][p] += w1 * y; a[2][p] += w2 * y; a[3][p] += w3 * y;
        }
    }
    #pragma unroll
    for (int p = 0; p < 8; p++) {
        int n = n0 + p;
        if (n < N) {
            size_t o = ((size_t)b*MAXN + n) * 512;
            #pragma unroll
            for (int r = 0; r < 4; r++) {
                float v = a[r][p];
                float g = 0.5f * v * (1.0f + erff(v * 0.70710678118654752f));
                H[o + tid + 128*r] = g;
            }
        }
    }
}

// ---------------- fc2: X += H @ W2(512x128) + b2 ---------------------------
__global__ void k_fc2(const float* __restrict__ H, const float* __restrict__ W,
                      const float* __restrict__ bias, float* __restrict__ X) {
    int b = blockIdx.y;
    int n0 = blockIdx.x * 8;
    int N = g_N;
    if (n0 >= N) return;
    __shared__ float sH[8][512];
    int tid = threadIdx.x;
    for (int idx = tid; idx < 8*512; idx += 128) {
        int p = idx >> 9, k = idx & 511;
        int n = n0 + p;
        sH[p][k] = (n < N) ? H[((size_t)b*MAXN + n)*512 + k] : 0.0f;
    }
    __syncthreads();
    float acc[8];
    float bs = bias[tid];
    #pragma unroll
    for (int p = 0; p < 8; p++) acc[p] = bs;
    for (int k = 0; k < 512; k++) {
        float w = W[k*128 + tid];
        #pragma unroll
        for (int p = 0; p < 8; p++) acc[p] += w * sH[p][k];
    }
    #pragma unroll
    for (int p = 0; p < 8; p++) {
        int n = n0 + p;
        if (n < N) X[((size_t)b*MAXN + n)*C + tid] += acc[p];
    }
}

// ---------------- prune stage 1 ---------------------------------------------
__global__ void k_prune1(float thresh, int pi) {
    int b = blockIdx.x;
    int t = threadIdx.x;
    int tc = g_N - 1;
    __shared__ int ssum[1024];
    __shared__ float sval[1024];
    __shared__ int sidx[1024];
    float am = -1e30f;
    int keep = 0;
    if (t < tc) {
        float s = 0.0f;
        #pragma unroll
        for (int h = 0; h < NH; h++) s += g_CLSP[(b*NH + h)*MAXN + 1 + t];
        am = s * 0.125f;
        keep = (am > thresh) ? 1 : 0;
    }
    ssum[t] = keep; sval[t] = am; sidx[t] = t;
    __syncthreads();
    for (int off = 512; off > 0; off >>= 1) {
        if (t < off) {
            if (sval[t + off] > sval[t] ||
                (sval[t + off] == sval[t] && sidx[t + off] < sidx[t])) {
                sval[t] = sval[t + off]; sidx[t] = sidx[t + off];
            }
        }
        __syncthreads();
    }
    int argidx = sidx[0];
    __syncthreads();
    for (int off = 1; off < 1024; off <<= 1) {
        int v = (t >= off) ? ssum[t - off] : 0;
        __syncthreads();
        ssum[t] += v;
        __syncthreads();
    }
    int total = ssum[1023];
    if (total > 0 && keep) g_order[b][ssum[t] - 1] = t;
    if (t == 0) {
        int cnt = total;
        if (total == 0) { g_order[b][0] = argidx; cnt = 1; }
        g_count[b] = cnt;
        atomicMax(&g_mk[pi], cnt);
    }
}

// ---------------- prune stage 2 ---------------------------------------------
__global__ void k_prune2(const float* __restrict__ Xold, float* __restrict__ Xnew,
                         const float* __restrict__ pos, int pi) {
    int b = blockIdx.y, c = threadIdx.x;
    int mk = g_mk[pi];
    if (blockIdx.x == 0) {
        Xnew[(size_t)b*MAXN*C + c] = Xold[(size_t)b*MAXN*C + c] + pos[c];
        if (b == 0 && c == 0) g_N = 1 + mk;
        return;
    }
    int j = blockIdx.x - 1;
    if (j >= mk) return;
    float v = 0.0f;
    if (j < g_count[b]) {
        int src = g_order[b][j];
        v = Xold[((size_t)b*MAXN + 1 + src)*C + c];
    }
    Xnew[((size_t)b*MAXN + 1 + j)*C + c] = v + pos[(1 + j)*C + c];
}

// ---------------- output copy ----------------------------------------------
__global__ void k_copy(const float* __restrict__ X, float* __restrict__ out,
                       int finalN, int total) {
    int idx = blockIdx.x * 256 + threadIdx.x;
    if (idx >= total) return;
    int per = finalN * C;
    int b = idx / per;
    int rem = idx - b * per;
    out[idx] = X[(size_t)b*MAXN*C + rem];
}

// ---------------- host orchestration ----------------------------------------
extern "C" void kernel_launch(void* const* d_in, const int* in_sizes, int n_in,
                              void* d_out, int out_size) {
    const float* conv_w   = (const float*)d_in[0];
    const float* conv_b   = (const float*)d_in[1];
    const float* cls_tok  = (const float*)d_in[2];
    const float* pos      = (const float*)d_in[3];
    const float* ln1_w    = (const float*)d_in[4];
    const float* ln1_b    = (const float*)d_in[5];
    const float* qkv_w    = (const float*)d_in[6];
    const float* qkv_b    = (const float*)d_in[7];
    const float* out_w    = (const float*)d_in[8];
    const float* out_b    = (const float*)d_in[9];
    const float* ln2_w    = (const float*)d_in[10];
    const float* ln2_b    = (const float*)d_in[11];
    const float* mlp_w1   = (const float*)d_in[12];
    const float* mlp_b1   = (const float*)d_in[13];
    const float* mlp_w2   = (const float*)d_in[14];
    const float* mlp_b2   = (const float*)d_in[15];
    const float* x        = (const float*)d_in[16];
    float* out = (float*)d_out;

    float *pX0, *pX1, *pY, *pQ, *pK, *pV, *pO, *pH;
    cudaGetSymbolAddress((void**)&pX0, g_X0);
    cudaGetSymbolAddress((void**)&pX1, g_X1);
    cudaGetSymbolAddress((void**)&pY,  g_Y);
    cudaGetSymbolAddress((void**)&pQ,  g_Q);
    cudaGetSymbolAddress((void**)&pK,  g_K);
    cudaGetSymbolAddress((void**)&pV,  g_V);
    cudaGetSymbolAddress((void**)&pO,  g_O);
    cudaGetSymbolAddress((void**)&pH,  g_H);

    const float THRESH[3] = {0.001f, 0.0012f, 0.0015f};

    k_init<<<1, 1>>>();
    k_transpose<<<768, 128>>>(conv_w);
    k_patch<<<dim3(128, BATCH), 128>>>(x, conv_b, pos, pX0);
    k_cls<<<BATCH, 128>>>(cls_tok, pos, pX0);

    float* cur = pX0;
    float* alt = pX1;
    dim3 gTok(MAXN, BATCH);
    dim3 gBlk(129, BATCH);
    dim3 gAtt((MAXN + 255)/256, BATCH*NH);

    for (int i = 0; i < L; i++) {
        k_ln   <<<gTok, 128>>>(cur, pY, ln1_w + i*C, ln1_b + i*C);
        k_qkv  <<<gBlk, 128>>>(pY, qkv_w + (size_t)i*C*384, qkv_b + i*384, pQ, pK, pV);
        k_attn2<<<gAtt, 256>>>(pQ, pK, pV, pO);
        k_proj <<<gBlk, 128>>>(pO, out_w + (size_t)i*C*C, out_b + i*C, cur);
        k_ln   <<<gTok, 128>>>(cur, pY, ln2_w + i*C, ln2_b + i*C);
        k_fc1  <<<gBlk, 128>>>(pY, mlp_w1 + (size_t)i*C*512, mlp_b1 + i*512, pH);
        k_fc2  <<<gBlk, 128>>>(pH, mlp_w2 + (size_t)i*512*C, mlp_b2 + i*C, cur);
        if (i < L - 1) {
            k_prune1<<<BATCH, 1024>>>(THRESH[i], i);
            k_prune2<<<gTok, 128>>>(cur, alt, pos, i);
            float* tmp = cur; cur = alt; alt = tmp;
        }
    }

    int finalN = out_size / (BATCH * C);
    int nblk = (out_size + 255) / 256;
    k_copy<<<nblk, 256>>>(cur, out, finalN, out_size);
}

// round 3
// speedup vs baseline: 17.0906x; 1.1641x over previous
#include <cuda_runtime.h>
#include <math.h>

#define MAXN 1025
#define BATCH 8
#define C 128
#define NH 8
#define HD 16
#define L 4
#define TK 128

// ---------------- device scratch (static, allocation-free) ----------------
__device__ float g_X0[BATCH*MAXN*C];
__device__ float g_X1[BATCH*MAXN*C];
__device__ float g_Q [BATCH*NH*MAXN*HD];
__device__ float g_K [BATCH*NH*MAXN*HD];
__device__ float g_V [BATCH*NH*MAXN*HD];
__device__ float g_O [BATCH*MAXN*C];
__device__ float g_H [BATCH*MAXN*512];
__device__ float g_CLSP[BATCH*NH*MAXN];
__device__ float g_WT[768*128];
__device__ int   g_order[BATCH][1024];
__device__ int   g_count[BATCH];
__device__ int   g_mk[3];
__device__ int   g_N;

// transpose conv_w (128,768) -> (768,128); also does global init
__global__ void k_transpose(const float* __restrict__ w) {
    int k = blockIdx.x, c = threadIdx.x;
    g_WT[k*128 + c] = w[c*768 + k];
    if (k == 0 && c == 0) {
        g_N = MAXN;
        g_mk[0] = 0; g_mk[1] = 0; g_mk[2] = 0;
    }
}

// ---------------- patch embed + cls row ------------------------------------
// grid (65, 8): x<64 -> 16 patches each; x==64 -> cls row
__global__ void __launch_bounds__(128) k_patch(
        const float* __restrict__ x, const float* __restrict__ cb,
        const float* __restrict__ cls, const float* __restrict__ pos,
        float* __restrict__ X) {
    int b = blockIdx.y;
    int tid = threadIdx.x;
    if (blockIdx.x == 64) {
        X[(size_t)b*MAXN*C + tid] = cls[tid] + pos[tid];
        return;
    }
    int t0 = blockIdx.x * 16;
    __shared__ float sPT[768][16];   // 48KB, token-major
    for (int v = tid; v < 768*16; v += 128) {
        int p = v & 15, k = v >> 4;
        int t = t0 + p;
        int ph = t >> 5, pw = t & 31;
        int ch = k >> 8, rem = k & 255, py = rem >> 4, px = rem & 15;
        sPT[k][p] = x[((size_t)(b*3 + ch)*512 + ph*16 + py)*512 + pw*16 + px];
    }
    __syncthreads();
    float acc[16];
    float bias = cb[tid];
    #pragma unroll
    for (int p = 0; p < 16; p++) acc[p] = bias;
    #pragma unroll 4
    for (int k = 0; k < 768; k++) {
        float w = g_WT[k*128 + tid];
        float y[16];
        *(float4*)&y[0]  = *(const float4*)&sPT[k][0];
        *(float4*)&y[4]  = *(const float4*)&sPT[k][4];
        *(float4*)&y[8]  = *(const float4*)&sPT[k][8];
        *(float4*)&y[12] = *(const float4*)&sPT[k][12];
        #pragma unroll
        for (int p = 0; p < 16; p++) acc[p] = fmaf(w, y[p], acc[p]);
    }
    #pragma unroll
    for (int p = 0; p < 16; p++) {
        int t = t0 + p;
        X[((size_t)b*MAXN + 1 + t)*C + tid] = acc[p] + pos[(1 + t)*C + tid];
    }
}

// ---------------- LN helper (16 tokens, 128 threads) -----------------------
// x[p] in regs (col = tid). Writes normalized y to sYT[tid][p4] (token-major).
#define LN16_BODY(lwp, lbp)                                                     \
    {                                                                           \
        _Pragma("unroll")                                                       \
        for (int p = 0; p < 16; p++) {                                          \
            float s = xv[p];                                                    \
            _Pragma("unroll")                                                   \
            for (int o = 16; o; o >>= 1) s += __shfl_xor_sync(~0u, s, o);       \
            if (!lane) sRed[0][wid][p] = s;                                     \
        }                                                                       \
        __syncthreads();                                                        \
        _Pragma("unroll")                                                       \
        for (int p = 0; p < 16; p++) {                                          \
            float mu = (sRed[0][0][p] + sRed[0][1][p] + sRed[0][2][p]           \
                        + sRed[0][3][p]) * 0.0078125f;                          \
            float d = xv[p] - mu; xv[p] = d;                                    \
            float s = d * d;                                                    \
            _Pragma("unroll")                                                   \
            for (int o = 16; o; o >>= 1) s += __shfl_xor_sync(~0u, s, o);       \
            if (!lane) sRed[1][wid][p] = s;                                     \
        }                                                                       \
        __syncthreads();                                                        \
        float wgt = (lwp)[tid], bia = (lbp)[tid];                               \
        _Pragma("unroll")                                                       \
        for (int p4 = 0; p4 < 4; p4++) {                                        \
            float4 pk;                                                          \
            float* pkf = (float*)&pk;                                           \
            _Pragma("unroll")                                                   \
            for (int j = 0; j < 4; j++) {                                       \
                int p = 4*p4 + j;                                               \
                float var = (sRed[1][0][p] + sRed[1][1][p] + sRed[1][2][p]      \
                             + sRed[1][3][p]) * 0.0078125f;                     \
                pkf[j] = xv[p] * rsqrtf(var + 1e-5f) * wgt + bia;               \
            }                                                                   \
            sYT[tid][p4] = pk;                                                  \
        }                                                                       \
        __syncthreads();                                                        \
    }

// ---------------- LN + qkv -> head-major Q,K,V [b,h,n,16] ------------------
__global__ void __launch_bounds__(128) k_qkvln(
        const float* __restrict__ X, const float* __restrict__ lw,
        const float* __restrict__ lb, const float* __restrict__ W,
        const float* __restrict__ bias,
        float* __restrict__ Qo, float* __restrict__ Ko, float* __restrict__ Vo) {
    int b = blockIdx.y;
    int n0 = blockIdx.x * 16;
    int N = g_N;
    if (n0 >= N) return;
    int tid = threadIdx.x, wid = tid >> 5, lane = tid & 31;
    __shared__ float4 sYT[128][4];
    __shared__ float sRed[2][4][16];
    float xv[16];
    #pragma unroll
    for (int p = 0; p < 16; p++) {
        int n = n0 + p;
        xv[p] = (n < N) ? X[((size_t)b*MAXN + n)*C + tid] : 0.0f;
    }
    LN16_BODY(lw, lb)
    float a0[16], a1[16], a2[16];
    float b0 = bias[tid], b1 = bias[tid + 128], b2 = bias[tid + 256];
    #pragma unroll
    for (int p = 0; p < 16; p++) { a0[p] = b0; a1[p] = b1; a2[p] = b2; }
    #pragma unroll 4
    for (int k = 0; k < 128; k++) {
        float w0 = W[k*384 + tid];
        float w1 = W[k*384 + 128 + tid];
        float w2 = W[k*384 + 256 + tid];
        float y[16];
        *(float4*)&y[0]  = sYT[k][0];
        *(float4*)&y[4]  = sYT[k][1];
        *(float4*)&y[8]  = sYT[k][2];
        *(float4*)&y[12] = sYT[k][3];
        #pragma unroll
        for (int p = 0; p < 16; p++) {
            a0[p] = fmaf(w0, y[p], a0[p]);
            a1[p] = fmaf(w1, y[p], a1[p]);
            a2[p] = fmaf(w2, y[p], a2[p]);
        }
    }
    int h = tid >> 4, d = tid & 15;
    size_t hb = (size_t)(b*NH + h)*MAXN;
    #pragma unroll
    for (int p = 0; p < 16; p++) {
        int n = n0 + p;
        if (n < N) {
            size_t o = (hb + n)*HD + d;
            Qo[o] = a0[p]; Ko[o] = a1[p]; Vo[o] = a2[p];
        }
    }
}

// ---------------- attention: 1 query/lane, ILP-4 dots, __expf --------------
// grid (9, B*NH), block 128
__global__ void __launch_bounds__(128) k_attn3(
        const float* __restrict__ Q, const float* __restrict__ K,
        const float* __restrict__ V, float* __restrict__ O) {
    int N = g_N;
    int bh = blockIdx.y;
    int b = bh >> 3, h = bh & 7;
    int q0 = blockIdx.x * 128;
    if (q0 >= N) return;
    int tid = threadIdx.x;
    __shared__ float4 sK[TK*4];
    __shared__ float4 sV[TK*4];
    const float4* K4 = (const float4*)(K + (size_t)bh*MAXN*HD);
    const float4* V4 = (const float4*)(V + (size_t)bh*MAXN*HD);
    int q = q0 + tid;

    float qv[16];
    if (q < N) {
        const float4* Q4 = (const float4*)(Q + ((size_t)bh*MAXN + q)*HD);
        float4 t0 = Q4[0], t1 = Q4[1], t2 = Q4[2], t3 = Q4[3];
        // prescale by 0.25 (exact power of two -> identical score bits)
        qv[0]=t0.x*0.25f; qv[1]=t0.y*0.25f; qv[2]=t0.z*0.25f; qv[3]=t0.w*0.25f;
        qv[4]=t1.x*0.25f; qv[5]=t1.y*0.25f; qv[6]=t1.z*0.25f; qv[7]=t1.w*0.25f;
        qv[8]=t2.x*0.25f; qv[9]=t2.y*0.25f; qv[10]=t2.z*0.25f; qv[11]=t2.w*0.25f;
        qv[12]=t3.x*0.25f; qv[13]=t3.y*0.25f; qv[14]=t3.z*0.25f; qv[15]=t3.w*0.25f;
    }

    float m_run = -1e30f, l_run = 0.0f;
    float acc[16];
    #pragma unroll
    for (int d = 0; d < 16; d++) acc[d] = 0.0f;

    int nt = (N + TK - 1) / TK;
    for (int t = 0; t < nt; t++) {
        int base = t * TK;
        int kn = min(TK, N - base);
        __syncthreads();
        for (int i = tid; i < kn*4; i += 128) {
            sK[i] = K4[base*4 + i];
            sV[i] = V4[base*4 + i];
        }
        __syncthreads();
        if (q < N) {
            for (int m = 0; m < kn; m++) {
                float4 k0 = sK[m*4], k1 = sK[m*4+1], k2 = sK[m*4+2], k3 = sK[m*4+3];
                float s0 = qv[0]*k0.x;  s0 = fmaf(qv[1], k0.y, s0);
                s0 = fmaf(qv[2], k0.z, s0); s0 = fmaf(qv[3], k0.w, s0);
                float s1 = qv[4]*k1.x;  s1 = fmaf(qv[5], k1.y, s1);
                s1 = fmaf(qv[6], k1.z, s1); s1 = fmaf(qv[7], k1.w, s1);
                float s2 = qv[8]*k2.x;  s2 = fmaf(qv[9], k2.y, s2);
                s2 = fmaf(qv[10], k2.z, s2); s2 = fmaf(qv[11], k2.w, s2);
                float s3 = qv[12]*k3.x; s3 = fmaf(qv[13], k3.y, s3);
                s3 = fmaf(qv[14], k3.z, s3); s3 = fmaf(qv[15], k3.w, s3);
                float s = (s0 + s1) + (s2 + s3);
                if (s > m_run) {
                    float corr = __expf(m_run - s);
                    l_run *= corr;
                    #pragma unroll
                    for (int d = 0; d < 16; d++) acc[d] *= corr;
                    m_run = s;
                }
                float e = __expf(s - m_run);
                l_run += e;
                float4 v0 = sV[m*4], v1 = sV[m*4+1], v2 = sV[m*4+2], v3 = sV[m*4+3];
                acc[0]=fmaf(e,v0.x,acc[0]); acc[1]=fmaf(e,v0.y,acc[1]);
                acc[2]=fmaf(e,v0.z,acc[2]); acc[3]=fmaf(e,v0.w,acc[3]);
                acc[4]=fmaf(e,v1.x,acc[4]); acc[5]=fmaf(e,v1.y,acc[5]);
                acc[6]=fmaf(e,v1.z,acc[6]); acc[7]=fmaf(e,v1.w,acc[7]);
                acc[8]=fmaf(e,v2.x,acc[8]); acc[9]=fmaf(e,v2.y,acc[9]);
                acc[10]=fmaf(e,v2.z,acc[10]); acc[11]=fmaf(e,v2.w,acc[11]);
                acc[12]=fmaf(e,v3.x,acc[12]); acc[13]=fmaf(e,v3.y,acc[13]);
                acc[14]=fmaf(e,v3.z,acc[14]); acc[15]=fmaf(e,v3.w,acc[15]);
            }
        }
    }

    if (q < N) {
        float inv = 1.0f / l_run;
        float4 k0 = K4[0], k1 = K4[1], k2 = K4[2], k3 = K4[3];
        float s0 = qv[0]*k0.x;  s0 = fmaf(qv[1], k0.y, s0);
        s0 = fmaf(qv[2], k0.z, s0); s0 = fmaf(qv[3], k0.w, s0);
        float s1 = qv[4]*k1.x;  s1 = fmaf(qv[5], k1.y, s1);
        s1 = fmaf(qv[6], k1.z, s1); s1 = fmaf(qv[7], k1.w, s1);
        float s2 = qv[8]*k2.x;  s2 = fmaf(qv[9], k2.y, s2);
        s2 = fmaf(qv[10], k2.z, s2); s2 = fmaf(qv[11], k2.w, s2);
        float s3 = qv[12]*k3.x; s3 = fmaf(qv[13], k3.y, s3);
        s3 = fmaf(qv[14], k3.z, s3); s3 = fmaf(qv[15], k3.w, s3);
        float sc = (s0 + s1) + (s2 + s3);
        g_CLSP[(size_t)bh*MAXN + q] = __expf(sc - m_run) * inv;
        float* op = O + ((size_t)b*MAXN + q)*C + h*HD;
        float4 o0 = make_float4(acc[0]*inv, acc[1]*inv, acc[2]*inv, acc[3]*inv);
        float4 o1 = make_float4(acc[4]*inv, acc[5]*inv, acc[6]*inv, acc[7]*inv);
        float4 o2 = make_float4(acc[8]*inv, acc[9]*inv, acc[10]*inv, acc[11]*inv);
        float4 o3 = make_float4(acc[12]*inv, acc[13]*inv, acc[14]*inv, acc[15]*inv);
        ((float4*)op)[0] = o0; ((float4*)op)[1] = o1;
        ((float4*)op)[2] = o2; ((float4*)op)[3] = o3;
    }
}

// ---------------- out proj: X += O @ W(128x128) + b (16 tokens) ------------
__global__ void __launch_bounds__(128) k_proj(
        const float* __restrict__ Oin, const float* __restrict__ W,
        const float* __restrict__ bias, float* __restrict__ X) {
    int b = blockIdx.y;
    int n0 = blockIdx.x * 16;
    int N = g_N;
    if (n0 >= N) return;
    int tid = threadIdx.x;
    __shared__ float sOT[128][16];
    const float4* O4 = (const float4*)Oin;
    for (int v = tid; v < 16*32; v += 128) {
        int p = v & 15, kq = v >> 4;
        int n = n0 + p;
        float4 o4 = (n < N) ? O4[((size_t)b*MAXN + n)*32 + kq]
                            : make_float4(0.f, 0.f, 0.f, 0.f);
        sOT[4*kq+0][p] = o4.x; sOT[4*kq+1][p] = o4.y;
        sOT[4*kq+2][p] = o4.z; sOT[4*kq+3][p] = o4.w;
    }
    __syncthreads();
    float acc[16];
    float bs = bias[tid];
    #pragma unroll
    for (int p = 0; p < 16; p++) acc[p] = bs;
    #pragma unroll 4
    for (int k = 0; k < 128; k++) {
        float w = W[k*128 + tid];
        float y[16];
        *(float4*)&y[0]  = *(const float4*)&sOT[k][0];
        *(float4*)&y[4]  = *(const float4*)&sOT[k][4];
        *(float4*)&y[8]  = *(const float4*)&sOT[k][8];
        *(float4*)&y[12] = *(const float4*)&sOT[k][12];
        #pragma unroll
        for (int p = 0; p < 16; p++) acc[p] = fmaf(w, y[p], acc[p]);
    }
    #pragma unroll
    for (int p = 0; p < 16; p++) {
        int n = n0 + p;
        if (n < N) X[((size_t)b*MAXN + n)*C + tid] += acc[p];
    }
}

// ---------------- LN + fc1 + exact gelu (16 tokens, 4 cols/thread) ---------
__global__ void __launch_bounds__(128) k_fc1ln(
        const float* __restrict__ X, const float* __restrict__ lw,
        const float* __restrict__ lb, const float* __restrict__ W,
        const float* __restrict__ bias, float* __restrict__ H) {
    int b = blockIdx.y;
    int n0 = blockIdx.x * 16;
    int N = g_N;
    if (n0 >= N) return;
    int tid = threadIdx.x, wid = tid >> 5, lane = tid & 31;
    __shared__ float4 sYT[128][4];
    __shared__ float sRed[2][4][16];
    float xv[16];
    #pragma unroll
    for (int p = 0; p < 16; p++) {
        int n = n0 + p;
        xv[p] = (n < N) ? X[((size_t)b*MAXN + n)*C + tid] : 0.0f;
    }
    LN16_BODY(lw, lb)
    const float4* W4 = (const float4*)W;
    float4 b4 = ((const float4*)bias)[tid];
    float a0[16], a1[16], a2[16], a3[16];
    #pragma unroll
    for (int p = 0; p < 16; p++) { a0[p]=b4.x; a1[p]=b4.y; a2[p]=b4.z; a3[p]=b4.w; }
    #pragma unroll 4
    for (int k = 0; k < 128; k++) {
        float4 w4 = W4[k*128 + tid];
        float y[16];
        *(float4*)&y[0]  = sYT[k][0];
        *(float4*)&y[4]  = sYT[k][1];
        *(float4*)&y[8]  = sYT[k][2];
        *(float4*)&y[12] = sYT[k][3];
        #pragma unroll
        for (int p = 0; p < 16; p++) {
            a0[p] = fmaf(w4.x, y[p], a0[p]);
            a1[p] = fmaf(w4.y, y[p], a1[p]);
            a2[p] = fmaf(w4.z, y[p], a2[p]);
            a3[p] = fmaf(w4.w, y[p], a3[p]);
        }
    }
    float4* H4 = (float4*)H;
    #pragma unroll
    for (int p = 0; p < 16; p++) {
        int n = n0 + p;
        if (n < N) {
            float4 hv;
            hv.x = 0.5f*a0[p]*(1.0f + erff(a0[p]*0.70710678118654752f));
            hv.y = 0.5f*a1[p]*(1.0f + erff(a1[p]*0.70710678118654752f));
            hv.z = 0.5f*a2[p]*(1.0f + erff(a2[p]*0.70710678118654752f));
            hv.w = 0.5f*a3[p]*(1.0f + erff(a3[p]*0.70710678118654752f));
            H4[((size_t)b*MAXN + n)*128 + tid] = hv;
        }
    }
}

// ---------------- fc2: X += H @ W2(512x128) + b2 (16 tokens) ---------------
__global__ void __launch_bounds__(128) k_fc2(
        const float* __restrict__ H, const float* __restrict__ W,
        const float* __restrict__ bias, float* __restrict__ X) {
    int b = blockIdx.y;
    int n0 = blockIdx.x * 16;
    int N = g_N;
    if (n0 >= N) return;
    int tid = threadIdx.x;
    __shared__ float sHT[512][16];   // 32KB
    const float4* H4 = (const float4*)H;
    for (int v = tid; v < 16*128; v += 128) {
        int p = v & 15, kq = v >> 4;
        int n = n0 + p;
        float4 h4 = (n < N) ? H4[((size_t)b*MAXN + n)*128 + kq]
                            : make_float4(0.f, 0.f, 0.f, 0.f);
        sHT[4*kq+0][p] = h4.x; sHT[4*kq+1][p] = h4.y;
        sHT[4*kq+2][p] = h4.z; sHT[4*kq+3][p] = h4.w;
    }
    __syncthreads();
    float acc[16];
    float bs = bias[tid];
    #pragma unroll
    for (int p = 0; p < 16; p++) acc[p] = bs;
    #pragma unroll 4
    for (int k = 0; k < 512; k++) {
        float w = W[k*128 + tid];
        float y[16];
        *(float4*)&y[0]  = *(const float4*)&sHT[k][0];
        *(float4*)&y[4]  = *(const float4*)&sHT[k][4];
        *(float4*)&y[8]  = *(const float4*)&sHT[k][8];
        *(float4*)&y[12] = *(const float4*)&sHT[k][12];
        #pragma unroll
        for (int p = 0; p < 16; p++) acc[p] = fmaf(w, y[p], acc[p]);
    }
    #pragma unroll
    for (int p = 0; p < 16; p++) {
        int n = n0 + p;
        if (n < N) X[((size_t)b*MAXN + n)*C + tid] += acc[p];
    }
}

// ---------------- prune stage 1 ---------------------------------------------
__global__ void k_prune1(float thresh, int pi) {
    int b = blockIdx.x;
    int t = threadIdx.x;
    int tc = g_N - 1;
    __shared__ int ssum[1024];
    __shared__ float sval[1024];
    __shared__ int sidx[1024];
    float am = -1e30f;
    int keep = 0;
    if (t < tc) {
        float s = 0.0f;
        #pragma unroll
        for (int h = 0; h < NH; h++) s += g_CLSP[(b*NH + h)*MAXN + 1 + t];
        am = s * 0.125f;
        keep = (am > thresh) ? 1 : 0;
    }
    ssum[t] = keep; sval[t] = am; sidx[t] = t;
    __syncthreads();
    for (int off = 512; off > 0; off >>= 1) {
        if (t < off) {
            if (sval[t + off] > sval[t] ||
                (sval[t + off] == sval[t] && sidx[t + off] < sidx[t])) {
                sval[t] = sval[t + off]; sidx[t] = sidx[t + off];
            }
        }
        __syncthreads();
    }
    int argidx = sidx[0];
    __syncthreads();
    for (int off = 1; off < 1024; off <<= 1) {
        int v = (t >= off) ? ssum[t - off] : 0;
        __syncthreads();
        ssum[t] += v;
        __syncthreads();
    }
    int total = ssum[1023];
    if (total > 0 && keep) g_order[b][ssum[t] - 1] = t;
    if (t == 0) {
        int cnt = total;
        if (total == 0) { g_order[b][0] = argidx; cnt = 1; }
        g_count[b] = cnt;
        atomicMax(&g_mk[pi], cnt);
    }
}

// ---------------- prune stage 2 ---------------------------------------------
__global__ void k_prune2(const float* __restrict__ Xold, float* __restrict__ Xnew,
                         const float* __restrict__ pos, int pi) {
    int b = blockIdx.y, c = threadIdx.x;
    int mk = g_mk[pi];
    if (blockIdx.x == 0) {
        Xnew[(size_t)b*MAXN*C + c] = Xold[(size_t)b*MAXN*C + c] + pos[c];
        if (b == 0 && c == 0) g_N = 1 + mk;
        return;
    }
    int j = blockIdx.x - 1;
    if (j >= mk) return;
    float v = 0.0f;
    if (j < g_count[b]) {
        int src = g_order[b][j];
        v = Xold[((size_t)b*MAXN + 1 + src)*C + c];
    }
    Xnew[((size_t)b*MAXN + 1 + j)*C + c] = v + pos[(1 + j)*C + c];
}

// ---------------- output copy ----------------------------------------------
__global__ void k_copy(const float* __restrict__ X, float* __restrict__ out,
                       int finalN, int total) {
    int idx = blockIdx.x * 256 + threadIdx.x;
    if (idx >= total) return;
    int per = finalN * C;
    int b = idx / per;
    int rem = idx - b * per;
    out[idx] = X[(size_t)b*MAXN*C + rem];
}

// ---------------- host orchestration ----------------------------------------
extern "C" void kernel_launch(void* const* d_in, const int* in_sizes, int n_in,
                              void* d_out, int out_size) {
    const float* conv_w   = (const float*)d_in[0];
    const float* conv_b   = (const float*)d_in[1];
    const float* cls_tok  = (const float*)d_in[2];
    const float* pos      = (const float*)d_in[3];
    const float* ln1_w    = (const float*)d_in[4];
    const float* ln1_b    = (const float*)d_in[5];
    const float* qkv_w    = (const float*)d_in[6];
    const float* qkv_b    = (const float*)d_in[7];
    const float* out_w    = (const float*)d_in[8];
    const float* out_b    = (const float*)d_in[9];
    const float* ln2_w    = (const float*)d_in[10];
    const float* ln2_b    = (const float*)d_in[11];
    const float* mlp_w1   = (const float*)d_in[12];
    const float* mlp_b1   = (const float*)d_in[13];
    const float* mlp_w2   = (const float*)d_in[14];
    const float* mlp_b2   = (const float*)d_in[15];
    const float* x        = (const float*)d_in[16];
    float* out = (float*)d_out;

    float *pX0, *pX1, *pQ, *pK, *pV, *pO, *pH;
    cudaGetSymbolAddress((void**)&pX0, g_X0);
    cudaGetSymbolAddress((void**)&pX1, g_X1);
    cudaGetSymbolAddress((void**)&pQ,  g_Q);
    cudaGetSymbolAddress((void**)&pK,  g_K);
    cudaGetSymbolAddress((void**)&pV,  g_V);
    cudaGetSymbolAddress((void**)&pO,  g_O);
    cudaGetSymbolAddress((void**)&pH,  g_H);

    const float THRESH[3] = {0.001f, 0.0012f, 0.0015f};

    k_transpose<<<768, 128>>>(conv_w);
    k_patch<<<dim3(65, BATCH), 128>>>(x, conv_b, cls_tok, pos, pX0);

    float* cur = pX0;
    float* alt = pX1;
    dim3 gBlk(65, BATCH);
    dim3 gAtt((MAXN + TK - 1)/TK, BATCH*NH);
    dim3 gTok(MAXN, BATCH);

    for (int i = 0; i < L; i++) {
        k_qkvln<<<gBlk, 128>>>(cur, ln1_w + i*C, ln1_b + i*C,
                               qkv_w + (size_t)i*C*384, qkv_b + i*384, pQ, pK, pV);
        k_attn3<<<gAtt, 128>>>(pQ, pK, pV, pO);
        k_proj <<<gBlk, 128>>>(pO, out_w + (size_t)i*C*C, out_b + i*C, cur);
        k_fc1ln<<<gBlk, 128>>>(cur, ln2_w + i*C, ln2_b + i*C,
                               mlp_w1 + (size_t)i*C*512, mlp_b1 + i*512, pH);
        k_fc2  <<<gBlk, 128>>>(pH, mlp_w2 + (size_t)i*512*C, mlp_b2 + i*C, cur);
        if (i < L - 1) {
            k_prune1<<<BATCH, 1024>>>(THRESH[i], i);
            k_prune2<<<gTok, 128>>>(cur, alt, pos, i);
            float* tmp = cur; cur = alt; alt = tmp;
        }
    }

    int finalN = out_size / (BATCH * C);
    int nblk = (out_size + 255) / 256;
    k_copy<<<nblk, 256>>>(cur, out, finalN, out_size);
}